// round 11
// baseline (speedup 1.0000x reference)
#include <cuda_runtime.h>
#include <cuda_fp16.h>
#include <math.h>
#include <stdint.h>

#define Bz 2
#define TX 1024
#define TY 4096
#define CC 768
#define HH 12
#define DD 64

// fp16 activations ([M][K] row-major)
__device__ __half gx_h[(size_t)Bz * TX * CC];
__device__ __half gy_h[(size_t)Bz * TY * CC];
__device__ __half go_h[(size_t)Bz * TX * CC];
// transposed weights [N][K] fp16
__device__ __half gwq_h[(size_t)CC * CC];
__device__ __half gwkv_h[(size_t)2 * CC * CC];
__device__ __half gwp_h[(size_t)CC * CC];
// attention operands fp16
__device__ __half q_h[(size_t)Bz * HH * TX * DD];
__device__ __half k_h[(size_t)Bz * HH * TY * DD];
__device__ __half vt_h[(size_t)Bz * HH * DD * TY];  // [b,h,d,t]

__device__ __forceinline__ uint32_t pack_h2(float a, float b) {
    __half2 h = __floats2half2_rn(a, b);
    return *reinterpret_cast<uint32_t*>(&h);
}

__device__ __forceinline__ void cp16(uint32_t saddr, const void* g) {
    asm volatile("cp.async.cg.shared.global [%0], [%1], 16;" :: "r"(saddr), "l"(g));
}

__device__ __forceinline__ void mma_h(float* c, const uint32_t* a, const uint32_t* b) {
    asm volatile(
        "mma.sync.aligned.m16n8k16.row.col.f32.f16.f16.f32 "
        "{%0,%1,%2,%3},{%4,%5,%6,%7},{%8,%9},{%0,%1,%2,%3};"
        : "+f"(c[0]), "+f"(c[1]), "+f"(c[2]), "+f"(c[3])
        : "r"(a[0]), "r"(a[1]), "r"(a[2]), "r"(a[3]), "r"(b[0]), "r"(b[1]));
}

// ---------------------------------------------------------------------------
// Fused prep: fcvt(x), fcvt(y), wtrans(Wq), wtrans(Wkv), wtrans(Wp) in one
// launch, dispatched by block-id range.
//   blocks [0,1536)        : x -> gx_h          (256 float4 / block)
//   blocks [1536,7680)     : y -> gy_h
//   blocks [7680,8256)     : Wq  24x24 tiles
//   blocks [8256,9408)     : Wkv 48x24 tiles
//   blocks [9408,9984)     : Wp  24x24 tiles
// ---------------------------------------------------------------------------
#define PREP_BLOCKS 9984

__global__ void __launch_bounds__(256)
prep(const float* __restrict__ x, const float* __restrict__ y,
     const float* __restrict__ Wq, const float* __restrict__ Wkv,
     const float* __restrict__ Wp)
{
    __shared__ float sm[32][33];
    int id = blockIdx.x;
    if (id < 7680) {
        const float* A;
        __half* O;
        int i;
        if (id < 1536) { A = x; O = gx_h; i = id * 256 + threadIdx.x; }
        else           { A = y; O = gy_h; i = (id - 1536) * 256 + threadIdx.x; }
        float4 v = ((const float4*)A)[i];
        ((uint2*)O)[i] = make_uint2(pack_h2(v.x, v.y), pack_h2(v.z, v.w));
        return;
    }
    id -= 7680;
    const float* W;
    __half* T;
    int N;
    if (id < 576)       { W = Wq;  T = gwq_h;  N = 768; }
    else if (id < 1728) { id -= 576;  W = Wkv; T = gwkv_h; N = 1536; }
    else                { id -= 1728; W = Wp;  T = gwp_h;  N = 768; }
    const int K = CC;
    int ntile = N / 32;
    int n0 = (id % ntile) * 32, k0 = (id / ntile) * 32;
    int tx = threadIdx.x & 31, ty = threadIdx.x >> 5;
#pragma unroll
    for (int i = 0; i < 4; i++)
        sm[ty + 8 * i][tx] = W[(size_t)(k0 + ty + 8 * i) * N + n0 + tx];
    __syncthreads();
#pragma unroll
    for (int i = 0; i < 4; i++)
        T[(size_t)(n0 + ty + 8 * i) * K + k0 + tx] = __float2half(sm[tx][ty + 8 * i]);
}

// ---------------------------------------------------------------------------
// fp16 HMMA GEMM core. CTA tile 128x128, 2-stage cp.async, K=768.
// Shared by the fused Q+KV launch (mode 0/1) and the proj launch (mode 2).
// ---------------------------------------------------------------------------
#define STG_SZ 32768u
#define GEMM_SMEM 65536u

struct GemmCfg {
    const __half* Ah;
    const __half* Bh;
    int m0, n0, mode;
};

__device__ __forceinline__ void gemm_core(
    const GemmCfg& cfg, float* __restrict__ Out, int Nout,
    const float* __restrict__ tvec, const float* __restrict__ invf,
    uint8_t* smem)
{
    const uint32_t sbase = (uint32_t)__cvta_generic_to_shared(smem);
    const int tid = threadIdx.x;
    const int wid = tid >> 5, lane = tid & 31;
    const int wm = wid & 1, wn = wid >> 1;
    const int m0 = cfg.m0, n0 = cfg.n0;
    const int lr = lane >> 2, lc = lane & 3;
    const __half* Ah = cfg.Ah;
    const __half* Bh = cfg.Bh;
    const int K = CC;

    float acc[4][4][4];
#pragma unroll
    for (int a = 0; a < 4; a++)
#pragma unroll
        for (int b = 0; b < 4; b++)
#pragma unroll
            for (int c = 0; c < 4; c++) acc[a][b][c] = 0.f;

    const int NCH = K / 64;  // 12

    auto issue = [&](int ch, int st) {
        const int k0 = ch * 64;
        const uint32_t sa = sbase + (uint32_t)st * STG_SZ;
        const uint32_t sb = sa + 16384u;
#pragma unroll
        for (int it = 0; it < 4; it++) {
            int i = tid + it * 256;
            int r = i >> 3, t = i & 7;
            uint32_t soff = (uint32_t)(r * 128 + ((t ^ (r & 7)) << 4));
            cp16(sa + soff, Ah + (size_t)(m0 + r) * K + k0 + t * 8);
            cp16(sb + soff, Bh + (size_t)(n0 + r) * K + k0 + t * 8);
        }
        asm volatile("cp.async.commit_group;");
    };

    issue(0, 0);
    for (int ch = 0; ch < NCH; ch++) {
        if (ch + 1 < NCH) {
            issue(ch + 1, (ch + 1) & 1);
            asm volatile("cp.async.wait_group 1;");
        } else {
            asm volatile("cp.async.wait_group 0;");
        }
        __syncthreads();

        uint8_t* sA = smem + (size_t)(ch & 1) * STG_SZ;
        uint8_t* sB = sA + 16384;
#pragma unroll
        for (int s = 0; s < 4; s++) {
            uint32_t bf[4][2];
#pragma unroll
            for (int nt = 0; nt < 4; nt++) {
                int n = wn * 32 + nt * 8 + lr;
                uint32_t base = (uint32_t)(n * 128) + 4u * lc;
                bf[nt][0] = *(uint32_t*)(sB + base + (((2 * s) ^ (n & 7)) << 4));
                bf[nt][1] = *(uint32_t*)(sB + base + (((2 * s + 1) ^ (n & 7)) << 4));
            }
#pragma unroll
            for (int mt = 0; mt < 4; mt++) {
                int m1 = wm * 64 + mt * 16 + lr;
                int m2 = m1 + 8;
                uint32_t b1 = (uint32_t)(m1 * 128) + 4u * lc;
                uint32_t b2 = (uint32_t)(m2 * 128) + 4u * lc;
                uint32_t af[4];
                af[0] = *(uint32_t*)(sA + b1 + (((2 * s) ^ (m1 & 7)) << 4));
                af[1] = *(uint32_t*)(sA + b2 + (((2 * s) ^ (m2 & 7)) << 4));
                af[2] = *(uint32_t*)(sA + b1 + (((2 * s + 1) ^ (m1 & 7)) << 4));
                af[3] = *(uint32_t*)(sA + b2 + (((2 * s + 1) ^ (m2 & 7)) << 4));
#pragma unroll
                for (int nt = 0; nt < 4; nt++) mma_h(acc[mt][nt], af, bf[nt]);
            }
        }
        __syncthreads();
    }

    // ---- epilogue: fragment cols (2lc, 2lc+1) are RoPE pairs ----
    const int mode = cfg.mode;
#pragma unroll
    for (int mt = 0; mt < 4; mt++) {
        int mA = m0 + wm * 64 + mt * 16 + lr;
#pragma unroll
        for (int half = 0; half < 2; half++) {
            int m = mA + half * 8;
            float pos = 0.f;
            int bb = 0, tt = 0;
            if (mode == 0) { bb = m / TX; tt = m % TX; pos = tvec[m]; }
            if (mode == 1) { bb = m / TY; tt = m % TY; pos = tvec[m]; }
#pragma unroll
            for (int nt = 0; nt < 4; nt++) {
                float c0 = acc[mt][nt][half * 2 + 0];
                float c1 = acc[mt][nt][half * 2 + 1];
                int col = n0 + wn * 32 + nt * 8 + 2 * lc;
                if (mode == 2) {
                    *(float2*)&Out[(size_t)m * Nout + col] = make_float2(c0, c1);
                } else if (mode == 0) {
                    int h = col / DD, dd = col % DD;
                    float f = pos * invf[dd >> 1];
                    float sn, cs;
                    sincosf(f, &sn, &cs);
                    size_t idx = ((size_t)(bb * HH + h) * TX + tt) * DD + dd;
                    *(uint32_t*)&q_h[idx] = pack_h2(c0 * cs - c1 * sn, c1 * cs + c0 * sn);
                } else {
                    if (col < CC) {
                        int h = col / DD, dd = col % DD;
                        float f = pos * invf[dd >> 1];
                        float sn, cs;
                        sincosf(f, &sn, &cs);
                        size_t idx = ((size_t)(bb * HH + h) * TY + tt) * DD + dd;
                        *(uint32_t*)&k_h[idx] = pack_h2(c0 * cs - c1 * sn, c1 * cs + c0 * sn);
                    } else {
                        int nv = col - CC;
                        int h = nv / DD, dd = nv % DD;
                        size_t i0 = ((size_t)(bb * HH + h) * DD + dd) * TY + tt;
                        vt_h[i0]      = __float2half(c0);
                        vt_h[i0 + TY] = __float2half(c1);
                    }
                }
            }
        }
    }
}

// Fused Q + KV projection GEMM. 1D grid of 96 + 768 = 864 CTAs.
__global__ void __launch_bounds__(256, 2)
gemm_qkv(const float* __restrict__ x_t, const float* __restrict__ y_t,
         const float* __restrict__ invf)
{
    extern __shared__ __align__(16) uint8_t smem[];
    int id = blockIdx.x;
    GemmCfg cfg;
    const float* tv;
    if (id < 96) {
        cfg.mode = 0;
        cfg.n0 = (id % 6) * 128;
        cfg.m0 = (id / 6) * 128;
        cfg.Ah = gx_h;
        cfg.Bh = gwq_h;
        tv = x_t;
    } else {
        id -= 96;
        cfg.mode = 1;
        cfg.n0 = (id % 12) * 128;
        cfg.m0 = (id / 12) * 128;
        cfg.Ah = gy_h;
        cfg.Bh = gwkv_h;
        tv = y_t;
    }
    gemm_core(cfg, nullptr, 0, tv, invf, smem);
}

// Output projection GEMM: out = go_h @ Wp^T, 96 CTAs.
__global__ void __launch_bounds__(256, 2)
gemm_proj(float* __restrict__ Out)
{
    extern __shared__ __align__(16) uint8_t smem[];
    GemmCfg cfg;
    cfg.mode = 2;
    cfg.n0 = (blockIdx.x % 6) * 128;
    cfg.m0 = (blockIdx.x / 6) * 128;
    cfg.Ah = go_h;
    cfg.Bh = gwp_h;
    gemm_core(cfg, Out, CC, nullptr, nullptr, smem);
}

// ---------------------------------------------------------------------------
// fp16 HMMA flash attention. 128-query tile, 256 threads (8 warps x 16 rows),
// 2-stage cp.async pipeline on K / V^T / y_t tiles.
// Grid (TX/128, H, B) = (8, 12, 2).
// ---------------------------------------------------------------------------
#define FST 16640u                 // stage stride: K 8192 + V 8192 + kt 256
#define FL_RNG (2u * FST)
#define FL_SMEM (FL_RNG + 32u)

__global__ void __launch_bounds__(256)
flash_mma(const float* __restrict__ xt, const float* __restrict__ yt,
          const int* __restrict__ p_dist, const int* __restrict__ p_mind)
{
    extern __shared__ __align__(16) uint8_t sm[];
    const uint32_t sbase = (uint32_t)__cvta_generic_to_shared(sm);
    int* rng = (int*)(sm + FL_RNG);

    const int tid = threadIdx.x;
    const int wid = tid >> 5, lane = tid & 31;
    const int lr = lane >> 2, lc = lane & 3;
    const int q0 = blockIdx.x * 128;
    const int h = blockIdx.y, b = blockIdx.z;
    const float distf = (float)p_dist[0];
    const float mindf = (float)p_mind[0];
    const size_t bh = (size_t)(b * HH + h);

    const __half* Qp = q_h + bh * TX * DD;
    const __half* Kp = k_h + bh * TY * DD;
    const __half* Vp = vt_h + bh * DD * TY;
    const float* Y = yt + (size_t)b * TY;

    const int r0 = q0 + wid * 16 + lr;
    const int r1 = r0 + 8;

    uint32_t qf[4][4];
#pragma unroll
    for (int ks2 = 0; ks2 < 4; ks2++) {
        qf[ks2][0] = *(const uint32_t*)&Qp[(size_t)r0 * DD + 16 * ks2 + 2 * lc];
        qf[ks2][1] = *(const uint32_t*)&Qp[(size_t)r1 * DD + 16 * ks2 + 2 * lc];
        qf[ks2][2] = *(const uint32_t*)&Qp[(size_t)r0 * DD + 16 * ks2 + 8 + 2 * lc];
        qf[ks2][3] = *(const uint32_t*)&Qp[(size_t)r1 * DD + 16 * ks2 + 8 + 2 * lc];
    }
    const float xr0 = xt[(size_t)b * TX + r0] - mindf;
    const float xr1 = xt[(size_t)b * TX + r1] - mindf;

    if (tid == 0) {
        float xmin = xt[(size_t)b * TX + q0] - mindf;
        float xmax = xt[(size_t)b * TX + q0 + 127] - mindf;
        int lo = 0, hi = TY;
        while (lo < hi) { int mid = (lo + hi) >> 1; if (Y[mid] >= xmin - distf) hi = mid; else lo = mid + 1; }
        rng[0] = lo & ~63;
        lo = 0; hi = TY;
        while (lo < hi) { int mid = (lo + hi) >> 1; if (Y[mid] > xmax) hi = mid; else lo = mid + 1; }
        rng[1] = lo;
    }
    __syncthreads();
    const int ksr = rng[0], ker = rng[1];

    // async fill of one key-tile (64 keys) into stage st
    auto issue = [&](int kb, int st) {
        const uint32_t sk = sbase + (uint32_t)st * FST;
        const uint32_t sv = sk + 8192u;
#pragma unroll
        for (int it = 0; it < 2; it++) {
            int i = tid + it * 256;          // 0..511
            int r = i >> 3, t = i & 7;
            uint32_t so = (uint32_t)(r * 128 + ((t ^ (r & 7)) << 4));
            cp16(sk + so, Kp + (size_t)(kb + r) * DD + t * 8);
            cp16(sv + so, Vp + (size_t)r * TY + kb + t * 8);
        }
        if (tid < 16) cp16(sk + 16384u + tid * 16u, Y + kb + tid * 4);
        asm volatile("cp.async.commit_group;");
    };

    float m0r = -1e30f, m1r = -1e30f, l0r = 0.f, l1r = 0.f;
    float o[8][4];
#pragma unroll
    for (int i = 0; i < 8; i++)
#pragma unroll
        for (int j = 0; j < 4; j++) o[i][j] = 0.f;

    if (ksr < ker) issue(ksr, 0);
    int st = 0;
    for (int kb = ksr; kb < ker; kb += 64, st ^= 1) {
        if (kb + 64 < ker) {
            issue(kb + 64, st ^ 1);
            asm volatile("cp.async.wait_group 1;");
        } else {
            asm volatile("cp.async.wait_group 0;");
        }
        __syncthreads();

        uint8_t* sk = sm + (size_t)st * FST;
        uint8_t* sv = sk + 8192;
        float* kt_s = (float*)(sk + 16384);

        // ---- S = Q K^T ----
        float s[8][4];
#pragma unroll
        for (int i = 0; i < 8; i++)
#pragma unroll
            for (int j = 0; j < 4; j++) s[i][j] = 0.f;
#pragma unroll
        for (int ks2 = 0; ks2 < 4; ks2++) {
#pragma unroll
            for (int nt = 0; nt < 8; nt++) {
                int n = nt * 8 + lr;
                uint32_t base = (uint32_t)(n * 128) + 4u * lc;
                uint32_t bf[2] = {*(uint32_t*)(sk + base + (((2 * ks2) ^ (n & 7)) << 4)),
                                  *(uint32_t*)(sk + base + (((2 * ks2 + 1) ^ (n & 7)) << 4))};
                mma_h(s[nt], qf[ks2], bf);
            }
        }

        // ---- mask + scale ----
#pragma unroll
        for (int nt = 0; nt < 8; nt++) {
#pragma unroll
            for (int j = 0; j < 2; j++) {
                float yv = kt_s[nt * 8 + 2 * lc + j];
                bool ok0 = (xr0 >= yv) && (xr0 <= yv + distf);
                bool ok1 = (xr1 >= yv) && (xr1 <= yv + distf);
                s[nt][j]     = ok0 ? s[nt][j] * 0.125f     : -1e30f;
                s[nt][j + 2] = ok1 ? s[nt][j + 2] * 0.125f : -1e30f;
            }
        }
        // ---- online softmax ----
        float mx0 = -1e30f, mx1 = -1e30f;
#pragma unroll
        for (int nt = 0; nt < 8; nt++) {
            mx0 = fmaxf(mx0, fmaxf(s[nt][0], s[nt][1]));
            mx1 = fmaxf(mx1, fmaxf(s[nt][2], s[nt][3]));
        }
        mx0 = fmaxf(mx0, __shfl_xor_sync(0xffffffffu, mx0, 1));
        mx0 = fmaxf(mx0, __shfl_xor_sync(0xffffffffu, mx0, 2));
        mx1 = fmaxf(mx1, __shfl_xor_sync(0xffffffffu, mx1, 1));
        mx1 = fmaxf(mx1, __shfl_xor_sync(0xffffffffu, mx1, 2));
        float mn0 = fmaxf(m0r, mx0), mn1 = fmaxf(m1r, mx1);
        float f0 = __expf(m0r - mn0), f1 = __expf(m1r - mn1);

        uint32_t pp[8][2];
        float sum0 = 0.f, sum1 = 0.f;
#pragma unroll
        for (int nt = 0; nt < 8; nt++) {
            float p00 = (s[nt][0] <= -1e29f) ? 0.f : __expf(s[nt][0] - mn0);
            float p01 = (s[nt][1] <= -1e29f) ? 0.f : __expf(s[nt][1] - mn0);
            float p10 = (s[nt][2] <= -1e29f) ? 0.f : __expf(s[nt][2] - mn1);
            float p11 = (s[nt][3] <= -1e29f) ? 0.f : __expf(s[nt][3] - mn1);
            sum0 += p00 + p01;
            sum1 += p10 + p11;
            pp[nt][0] = pack_h2(p00, p01);
            pp[nt][1] = pack_h2(p10, p11);
        }
        sum0 += __shfl_xor_sync(0xffffffffu, sum0, 1);
        sum0 += __shfl_xor_sync(0xffffffffu, sum0, 2);
        sum1 += __shfl_xor_sync(0xffffffffu, sum1, 1);
        sum1 += __shfl_xor_sync(0xffffffffu, sum1, 2);
        l0r = l0r * f0 + sum0;
        l1r = l1r * f1 + sum1;
        m0r = mn0;
        m1r = mn1;
#pragma unroll
        for (int nd = 0; nd < 8; nd++) {
            o[nd][0] *= f0; o[nd][1] *= f0;
            o[nd][2] *= f1; o[nd][3] *= f1;
        }

        // ---- O += P V ----
#pragma unroll
        for (int kp = 0; kp < 4; kp++) {
            uint32_t af[4] = {pp[2 * kp][0], pp[2 * kp][1], pp[2 * kp + 1][0], pp[2 * kp + 1][1]};
#pragma unroll
            for (int nd = 0; nd < 8; nd++) {
                int n = nd * 8 + lr;
                uint32_t base = (uint32_t)(n * 128) + 4u * lc;
                uint32_t bf[2] = {*(uint32_t*)(sv + base + (((2 * kp) ^ (n & 7)) << 4)),
                                  *(uint32_t*)(sv + base + (((2 * kp + 1) ^ (n & 7)) << 4))};
                mma_h(o[nd], af, bf);
            }
        }
        __syncthreads();
    }

    // ---- epilogue: O/l -> go_h fp16 ----
    float rc0 = (l0r > 0.f) ? 1.f / l0r : 0.f;
    float rc1 = (l1r > 0.f) ? 1.f / l1r : 0.f;
#pragma unroll
    for (int nd = 0; nd < 8; nd++) {
        int d0 = nd * 8 + 2 * lc;
        size_t i0 = ((size_t)b * TX + r0) * CC + h * DD + d0;
        *(uint32_t*)&go_h[i0] = pack_h2(o[nd][0] * rc0, o[nd][1] * rc0);
        size_t i1 = ((size_t)b * TX + r1) * CC + h * DD + d0;
        *(uint32_t*)&go_h[i1] = pack_h2(o[nd][2] * rc1, o[nd][3] * rc1);
    }
}

extern "C" void kernel_launch(void* const* d_in, const int* in_sizes, int n_in,
                              void* d_out, int out_size) {
    const float* x    = (const float*)d_in[0];
    const float* x_t  = (const float*)d_in[1];
    const float* y    = (const float*)d_in[2];
    const float* y_t  = (const float*)d_in[3];
    const int*   dist = (const int*)d_in[4];
    const int*   mind = (const int*)d_in[5];
    const float* Wq   = (const float*)d_in[6];
    const float* Wkv  = (const float*)d_in[7];
    const float* Wpr  = (const float*)d_in[8];
    const float* invf = (const float*)d_in[9];
    float* out = (float*)d_out;

    cudaFuncSetAttribute(gemm_qkv, cudaFuncAttributeMaxDynamicSharedMemorySize, GEMM_SMEM);
    cudaFuncSetAttribute(gemm_proj, cudaFuncAttributeMaxDynamicSharedMemorySize, GEMM_SMEM);
    cudaFuncSetAttribute(flash_mma, cudaFuncAttributeMaxDynamicSharedMemorySize, FL_SMEM);

    // 1) fused prep: fp16 conversions + weight transposes
    prep<<<PREP_BLOCKS, 256>>>(x, y, Wq, Wkv, Wpr);
    // 2) fused Q + KV projections (RoPE in epilogue; V transposed)
    gemm_qkv<<<96 + 768, 256, GEMM_SMEM>>>(x_t, y_t, invf);
    // 3) windowed flash attention (128-query tiles, cp.async pipelined)
    flash_mma<<<dim3(TX / 128, HH, Bz), 256, FL_SMEM>>>(x_t, y_t, dist, mind);
    // 4) output projection
    gemm_proj<<<96, 256, GEMM_SMEM>>>(out);
}

// round 12
// speedup vs baseline: 1.5877x; 1.5877x over previous
#include <cuda_runtime.h>
#include <cuda_fp16.h>
#include <math.h>
#include <stdint.h>

#define Bz 2
#define TX 1024
#define TY 4096
#define CC 768
#define HH 12
#define DD 64

// fp16 activations ([M][K] row-major)
__device__ __half gx_h[(size_t)Bz * TX * CC];
__device__ __half gy_h[(size_t)Bz * TY * CC];
__device__ __half go_h[(size_t)Bz * TX * CC];
// transposed weights [N][K] fp16
__device__ __half gwq_h[(size_t)CC * CC];
__device__ __half gwkv_h[(size_t)2 * CC * CC];
__device__ __half gwp_h[(size_t)CC * CC];
// attention operands fp16
__device__ __half q_h[(size_t)Bz * HH * TX * DD];
__device__ __half k_h[(size_t)Bz * HH * TY * DD];
__device__ __half vt_h[(size_t)Bz * HH * DD * TY];  // [b,h,d,t]

__device__ __forceinline__ uint32_t pack_h2(float a, float b) {
    __half2 h = __floats2half2_rn(a, b);
    return *reinterpret_cast<uint32_t*>(&h);
}

__device__ __forceinline__ void cp16(uint32_t saddr, const void* g) {
    asm volatile("cp.async.cg.shared.global [%0], [%1], 16;" :: "r"(saddr), "l"(g));
}

__device__ __forceinline__ void mma_h(float* c, const uint32_t* a, const uint32_t* b) {
    asm volatile(
        "mma.sync.aligned.m16n8k16.row.col.f32.f16.f16.f32 "
        "{%0,%1,%2,%3},{%4,%5,%6,%7},{%8,%9},{%0,%1,%2,%3};"
        : "+f"(c[0]), "+f"(c[1]), "+f"(c[2]), "+f"(c[3])
        : "r"(a[0]), "r"(a[1]), "r"(a[2]), "r"(a[3]), "r"(b[0]), "r"(b[1]));
}

// ---------------------------------------------------------------------------
// Fused prep (single launch): fcvt(x), fcvt(y), wtrans(Wq/Wkv/Wp).
//   blocks [0,1536)    : x -> gx_h (256 float4 / block)
//   blocks [1536,7680) : y -> gy_h
//   blocks [7680,8256) : Wq tiles   [8256,9408): Wkv   [9408,9984): Wp
// ---------------------------------------------------------------------------
#define PREP_BLOCKS 9984

__global__ void __launch_bounds__(256)
prep(const float* __restrict__ x, const float* __restrict__ y,
     const float* __restrict__ Wq, const float* __restrict__ Wkv,
     const float* __restrict__ Wp)
{
    __shared__ float sm[32][33];
    int id = blockIdx.x;
    if (id < 7680) {
        const float* A;
        __half* O;
        int i;
        if (id < 1536) { A = x; O = gx_h; i = id * 256 + threadIdx.x; }
        else           { A = y; O = gy_h; i = (id - 1536) * 256 + threadIdx.x; }
        float4 v = ((const float4*)A)[i];
        ((uint2*)O)[i] = make_uint2(pack_h2(v.x, v.y), pack_h2(v.z, v.w));
        return;
    }
    id -= 7680;
    const float* W;
    __half* T;
    int N;
    if (id < 576)       { W = Wq;  T = gwq_h;  N = 768; }
    else if (id < 1728) { id -= 576;  W = Wkv; T = gwkv_h; N = 1536; }
    else                { id -= 1728; W = Wp;  T = gwp_h;  N = 768; }
    const int K = CC;
    int ntile = N / 32;
    int n0 = (id % ntile) * 32, k0 = (id / ntile) * 32;
    int tx = threadIdx.x & 31, ty = threadIdx.x >> 5;
#pragma unroll
    for (int i = 0; i < 4; i++)
        sm[ty + 8 * i][tx] = W[(size_t)(k0 + ty + 8 * i) * N + n0 + tx];
    __syncthreads();
#pragma unroll
    for (int i = 0; i < 4; i++)
        T[(size_t)(n0 + ty + 8 * i) * K + k0 + tx] = __float2half(sm[tx][ty + 8 * i]);
}

// ---------------------------------------------------------------------------
// fp16 HMMA GEMM (templated MODE, as in the 166us build): CTA tile 128x128,
// 2-stage cp.async, K=768.
// MODE 0: RoPE -> q_h   MODE 1: K(RoPE)->k_h, V->vt_h   MODE 2: -> Out fp32
// ---------------------------------------------------------------------------
#define STG_SZ 32768u
#define GEMM_SMEM 65536u

template <int MODE>
__global__ void __launch_bounds__(256, 2)
gemm_mma(const __half* __restrict__ Ah, const __half* __restrict__ Bh,
         float* __restrict__ Out, int M, int N, int K,
         const float* __restrict__ tvec, const float* __restrict__ invf)
{
    extern __shared__ __align__(16) uint8_t smem[];
    const uint32_t sbase = (uint32_t)__cvta_generic_to_shared(smem);
    const int tid = threadIdx.x;
    const int wid = tid >> 5, lane = tid & 31;
    const int wm = wid & 1, wn = wid >> 1;
    const int m0 = blockIdx.y * 128, n0 = blockIdx.x * 128;
    const int lr = lane >> 2, lc = lane & 3;

    float acc[4][4][4];
#pragma unroll
    for (int a = 0; a < 4; a++)
#pragma unroll
        for (int b = 0; b < 4; b++)
#pragma unroll
            for (int c = 0; c < 4; c++) acc[a][b][c] = 0.f;

    const int NCH = K / 64;  // 12

    auto issue = [&](int ch, int st) {
        const int k0 = ch * 64;
        const uint32_t sa = sbase + (uint32_t)st * STG_SZ;
        const uint32_t sb = sa + 16384u;
#pragma unroll
        for (int it = 0; it < 4; it++) {
            int i = tid + it * 256;
            int r = i >> 3, t = i & 7;
            uint32_t soff = (uint32_t)(r * 128 + ((t ^ (r & 7)) << 4));
            cp16(sa + soff, Ah + (size_t)(m0 + r) * K + k0 + t * 8);
            cp16(sb + soff, Bh + (size_t)(n0 + r) * K + k0 + t * 8);
        }
        asm volatile("cp.async.commit_group;");
    };

    issue(0, 0);
    for (int ch = 0; ch < NCH; ch++) {
        if (ch + 1 < NCH) {
            issue(ch + 1, (ch + 1) & 1);
            asm volatile("cp.async.wait_group 1;");
        } else {
            asm volatile("cp.async.wait_group 0;");
        }
        __syncthreads();

        uint8_t* sA = smem + (size_t)(ch & 1) * STG_SZ;
        uint8_t* sB = sA + 16384;
#pragma unroll
        for (int s = 0; s < 4; s++) {
            uint32_t bf[4][2];
#pragma unroll
            for (int nt = 0; nt < 4; nt++) {
                int n = wn * 32 + nt * 8 + lr;
                uint32_t base = (uint32_t)(n * 128) + 4u * lc;
                bf[nt][0] = *(uint32_t*)(sB + base + (((2 * s) ^ (n & 7)) << 4));
                bf[nt][1] = *(uint32_t*)(sB + base + (((2 * s + 1) ^ (n & 7)) << 4));
            }
#pragma unroll
            for (int mt = 0; mt < 4; mt++) {
                int m1 = wm * 64 + mt * 16 + lr;
                int m2 = m1 + 8;
                uint32_t b1 = (uint32_t)(m1 * 128) + 4u * lc;
                uint32_t b2 = (uint32_t)(m2 * 128) + 4u * lc;
                uint32_t af[4];
                af[0] = *(uint32_t*)(sA + b1 + (((2 * s) ^ (m1 & 7)) << 4));
                af[1] = *(uint32_t*)(sA + b2 + (((2 * s) ^ (m2 & 7)) << 4));
                af[2] = *(uint32_t*)(sA + b1 + (((2 * s + 1) ^ (m1 & 7)) << 4));
                af[3] = *(uint32_t*)(sA + b2 + (((2 * s + 1) ^ (m2 & 7)) << 4));
#pragma unroll
                for (int nt = 0; nt < 4; nt++) mma_h(acc[mt][nt], af, bf[nt]);
            }
        }
        __syncthreads();
    }

    // ---- epilogue: fragment cols (2lc, 2lc+1) are RoPE pairs ----
#pragma unroll
    for (int mt = 0; mt < 4; mt++) {
        int mA = m0 + wm * 64 + mt * 16 + lr;
#pragma unroll
        for (int half = 0; half < 2; half++) {
            int m = mA + half * 8;
            float pos = 0.f;
            int bb = 0, tt = 0;
            if (MODE == 0) { bb = m / TX; tt = m % TX; pos = tvec[m]; }
            if (MODE == 1) { bb = m / TY; tt = m % TY; pos = tvec[m]; }
#pragma unroll
            for (int nt = 0; nt < 4; nt++) {
                float c0 = acc[mt][nt][half * 2 + 0];
                float c1 = acc[mt][nt][half * 2 + 1];
                int col = n0 + wn * 32 + nt * 8 + 2 * lc;
                if (MODE == 2) {
                    *(float2*)&Out[(size_t)m * N + col] = make_float2(c0, c1);
                } else if (MODE == 0) {
                    int h = col / DD, dd = col % DD;
                    float f = pos * invf[dd >> 1];
                    float sn, cs;
                    sincosf(f, &sn, &cs);
                    size_t idx = ((size_t)(bb * HH + h) * TX + tt) * DD + dd;
                    *(uint32_t*)&q_h[idx] = pack_h2(c0 * cs - c1 * sn, c1 * cs + c0 * sn);
                } else {
                    if (col < CC) {
                        int h = col / DD, dd = col % DD;
                        float f = pos * invf[dd >> 1];
                        float sn, cs;
                        sincosf(f, &sn, &cs);
                        size_t idx = ((size_t)(bb * HH + h) * TY + tt) * DD + dd;
                        *(uint32_t*)&k_h[idx] = pack_h2(c0 * cs - c1 * sn, c1 * cs + c0 * sn);
                    } else {
                        int nv = col - CC;
                        int h = nv / DD, dd = nv % DD;
                        size_t i0 = ((size_t)(bb * HH + h) * DD + dd) * TY + tt;
                        vt_h[i0]      = __float2half(c0);
                        vt_h[i0 + TY] = __float2half(c1);
                    }
                }
            }
        }
    }
}

// ---------------------------------------------------------------------------
// fp16 HMMA flash attention. 64-query tile, 128 threads (4 warps x 16 rows),
// 2-stage cp.async pipeline on K / V^T / y_t tiles. Grid (TX/64, H, B) = 384.
// ---------------------------------------------------------------------------
#define FST 16640u                 // stage: K 8192 + V 8192 + kt 256
#define FL_RNG (2u * FST)
#define FL_SMEM (FL_RNG + 32u)

__global__ void __launch_bounds__(128)
flash_mma(const float* __restrict__ xt, const float* __restrict__ yt,
          const int* __restrict__ p_dist, const int* __restrict__ p_mind)
{
    extern __shared__ __align__(16) uint8_t sm[];
    const uint32_t sbase = (uint32_t)__cvta_generic_to_shared(sm);
    int* rng = (int*)(sm + FL_RNG);

    const int tid = threadIdx.x;
    const int wid = tid >> 5, lane = tid & 31;
    const int lr = lane >> 2, lc = lane & 3;
    const int q0 = blockIdx.x * 64;
    const int h = blockIdx.y, b = blockIdx.z;
    const float distf = (float)p_dist[0];
    const float mindf = (float)p_mind[0];
    const size_t bh = (size_t)(b * HH + h);

    const __half* Qp = q_h + bh * TX * DD;
    const __half* Kp = k_h + bh * TY * DD;
    const __half* Vp = vt_h + bh * DD * TY;
    const float* Y = yt + (size_t)b * TY;

    const int r0 = q0 + wid * 16 + lr;
    const int r1 = r0 + 8;

    uint32_t qf[4][4];
#pragma unroll
    for (int ks2 = 0; ks2 < 4; ks2++) {
        qf[ks2][0] = *(const uint32_t*)&Qp[(size_t)r0 * DD + 16 * ks2 + 2 * lc];
        qf[ks2][1] = *(const uint32_t*)&Qp[(size_t)r1 * DD + 16 * ks2 + 2 * lc];
        qf[ks2][2] = *(const uint32_t*)&Qp[(size_t)r0 * DD + 16 * ks2 + 8 + 2 * lc];
        qf[ks2][3] = *(const uint32_t*)&Qp[(size_t)r1 * DD + 16 * ks2 + 8 + 2 * lc];
    }
    const float xr0 = xt[(size_t)b * TX + r0] - mindf;
    const float xr1 = xt[(size_t)b * TX + r1] - mindf;

    if (tid == 0) {
        float xmin = xt[(size_t)b * TX + q0] - mindf;
        float xmax = xt[(size_t)b * TX + q0 + 63] - mindf;
        int lo = 0, hi = TY;
        while (lo < hi) { int mid = (lo + hi) >> 1; if (Y[mid] >= xmin - distf) hi = mid; else lo = mid + 1; }
        rng[0] = lo & ~63;
        lo = 0; hi = TY;
        while (lo < hi) { int mid = (lo + hi) >> 1; if (Y[mid] > xmax) hi = mid; else lo = mid + 1; }
        rng[1] = lo;
    }
    __syncthreads();
    const int ksr = rng[0], ker = rng[1];

    // async fill of one 64-key tile into stage st
    auto issue = [&](int kb, int st) {
        const uint32_t sk = sbase + (uint32_t)st * FST;
        const uint32_t sv = sk + 8192u;
#pragma unroll
        for (int it = 0; it < 4; it++) {
            int i = tid + it * 128;          // 0..511
            int r = i >> 3, t = i & 7;
            uint32_t so = (uint32_t)(r * 128 + ((t ^ (r & 7)) << 4));
            cp16(sk + so, Kp + (size_t)(kb + r) * DD + t * 8);
            cp16(sv + so, Vp + (size_t)r * TY + kb + t * 8);
        }
        if (tid < 16) cp16(sk + 16384u + tid * 16u, Y + kb + tid * 4);
        asm volatile("cp.async.commit_group;");
    };

    float m0r = -1e30f, m1r = -1e30f, l0r = 0.f, l1r = 0.f;
    float o[8][4];
#pragma unroll
    for (int i = 0; i < 8; i++)
#pragma unroll
        for (int j = 0; j < 4; j++) o[i][j] = 0.f;

    if (ksr < ker) issue(ksr, 0);
    int st = 0;
    for (int kb = ksr; kb < ker; kb += 64, st ^= 1) {
        if (kb + 64 < ker) {
            issue(kb + 64, st ^ 1);
            asm volatile("cp.async.wait_group 1;");
        } else {
            asm volatile("cp.async.wait_group 0;");
        }
        __syncthreads();

        uint8_t* sk = sm + (size_t)st * FST;
        uint8_t* sv = sk + 8192;
        float* kt_s = (float*)(sk + 16384);

        // ---- S = Q K^T ----
        float s[8][4];
#pragma unroll
        for (int i = 0; i < 8; i++)
#pragma unroll
            for (int j = 0; j < 4; j++) s[i][j] = 0.f;
#pragma unroll
        for (int ks2 = 0; ks2 < 4; ks2++) {
#pragma unroll
            for (int nt = 0; nt < 8; nt++) {
                int n = nt * 8 + lr;
                uint32_t base = (uint32_t)(n * 128) + 4u * lc;
                uint32_t bf[2] = {*(uint32_t*)(sk + base + (((2 * ks2) ^ (n & 7)) << 4)),
                                  *(uint32_t*)(sk + base + (((2 * ks2 + 1) ^ (n & 7)) << 4))};
                mma_h(s[nt], qf[ks2], bf);
            }
        }

        // ---- mask + scale ----
#pragma unroll
        for (int nt = 0; nt < 8; nt++) {
#pragma unroll
            for (int j = 0; j < 2; j++) {
                float yv = kt_s[nt * 8 + 2 * lc + j];
                bool ok0 = (xr0 >= yv) && (xr0 <= yv + distf);
                bool ok1 = (xr1 >= yv) && (xr1 <= yv + distf);
                s[nt][j]     = ok0 ? s[nt][j] * 0.125f     : -1e30f;
                s[nt][j + 2] = ok1 ? s[nt][j + 2] * 0.125f : -1e30f;
            }
        }
        // ---- online softmax ----
        float mx0 = -1e30f, mx1 = -1e30f;
#pragma unroll
        for (int nt = 0; nt < 8; nt++) {
            mx0 = fmaxf(mx0, fmaxf(s[nt][0], s[nt][1]));
            mx1 = fmaxf(mx1, fmaxf(s[nt][2], s[nt][3]));
        }
        mx0 = fmaxf(mx0, __shfl_xor_sync(0xffffffffu, mx0, 1));
        mx0 = fmaxf(mx0, __shfl_xor_sync(0xffffffffu, mx0, 2));
        mx1 = fmaxf(mx1, __shfl_xor_sync(0xffffffffu, mx1, 1));
        mx1 = fmaxf(mx1, __shfl_xor_sync(0xffffffffu, mx1, 2));
        float mn0 = fmaxf(m0r, mx0), mn1 = fmaxf(m1r, mx1);
        float f0 = __expf(m0r - mn0), f1 = __expf(m1r - mn1);

        uint32_t pp[8][2];
        float sum0 = 0.f, sum1 = 0.f;
#pragma unroll
        for (int nt = 0; nt < 8; nt++) {
            float p00 = (s[nt][0] <= -1e29f) ? 0.f : __expf(s[nt][0] - mn0);
            float p01 = (s[nt][1] <= -1e29f) ? 0.f : __expf(s[nt][1] - mn0);
            float p10 = (s[nt][2] <= -1e29f) ? 0.f : __expf(s[nt][2] - mn1);
            float p11 = (s[nt][3] <= -1e29f) ? 0.f : __expf(s[nt][3] - mn1);
            sum0 += p00 + p01;
            sum1 += p10 + p11;
            pp[nt][0] = pack_h2(p00, p01);
            pp[nt][1] = pack_h2(p10, p11);
        }
        sum0 += __shfl_xor_sync(0xffffffffu, sum0, 1);
        sum0 += __shfl_xor_sync(0xffffffffu, sum0, 2);
        sum1 += __shfl_xor_sync(0xffffffffu, sum1, 1);
        sum1 += __shfl_xor_sync(0xffffffffu, sum1, 2);
        l0r = l0r * f0 + sum0;
        l1r = l1r * f1 + sum1;
        m0r = mn0;
        m1r = mn1;
#pragma unroll
        for (int nd = 0; nd < 8; nd++) {
            o[nd][0] *= f0; o[nd][1] *= f0;
            o[nd][2] *= f1; o[nd][3] *= f1;
        }

        // ---- O += P V ----
#pragma unroll
        for (int kp = 0; kp < 4; kp++) {
            uint32_t af[4] = {pp[2 * kp][0], pp[2 * kp][1], pp[2 * kp + 1][0], pp[2 * kp + 1][1]};
#pragma unroll
            for (int nd = 0; nd < 8; nd++) {
                int n = nd * 8 + lr;
                uint32_t base = (uint32_t)(n * 128) + 4u * lc;
                uint32_t bf[2] = {*(uint32_t*)(sv + base + (((2 * kp) ^ (n & 7)) << 4)),
                                  *(uint32_t*)(sv + base + (((2 * kp + 1) ^ (n & 7)) << 4))};
                mma_h(o[nd], af, bf);
            }
        }
        __syncthreads();
    }

    // ---- epilogue: O/l -> go_h fp16 ----
    float rc0 = (l0r > 0.f) ? 1.f / l0r : 0.f;
    float rc1 = (l1r > 0.f) ? 1.f / l1r : 0.f;
#pragma unroll
    for (int nd = 0; nd < 8; nd++) {
        int d0 = nd * 8 + 2 * lc;
        size_t i0 = ((size_t)b * TX + r0) * CC + h * DD + d0;
        *(uint32_t*)&go_h[i0] = pack_h2(o[nd][0] * rc0, o[nd][1] * rc0);
        size_t i1 = ((size_t)b * TX + r1) * CC + h * DD + d0;
        *(uint32_t*)&go_h[i1] = pack_h2(o[nd][2] * rc1, o[nd][3] * rc1);
    }
}

extern "C" void kernel_launch(void* const* d_in, const int* in_sizes, int n_in,
                              void* d_out, int out_size) {
    const float* x    = (const float*)d_in[0];
    const float* x_t  = (const float*)d_in[1];
    const float* y    = (const float*)d_in[2];
    const float* y_t  = (const float*)d_in[3];
    const int*   dist = (const int*)d_in[4];
    const int*   mind = (const int*)d_in[5];
    const float* Wq   = (const float*)d_in[6];
    const float* Wkv  = (const float*)d_in[7];
    const float* Wpr  = (const float*)d_in[8];
    const float* invf = (const float*)d_in[9];
    float* out = (float*)d_out;

    __half *p_gx, *p_gy, *p_go, *p_wq, *p_wkv, *p_wp;
    cudaGetSymbolAddress((void**)&p_gx, gx_h);
    cudaGetSymbolAddress((void**)&p_gy, gy_h);
    cudaGetSymbolAddress((void**)&p_go, go_h);
    cudaGetSymbolAddress((void**)&p_wq, gwq_h);
    cudaGetSymbolAddress((void**)&p_wkv, gwkv_h);
    cudaGetSymbolAddress((void**)&p_wp, gwp_h);

    cudaFuncSetAttribute(gemm_mma<0>, cudaFuncAttributeMaxDynamicSharedMemorySize, GEMM_SMEM);
    cudaFuncSetAttribute(gemm_mma<1>, cudaFuncAttributeMaxDynamicSharedMemorySize, GEMM_SMEM);
    cudaFuncSetAttribute(gemm_mma<2>, cudaFuncAttributeMaxDynamicSharedMemorySize, GEMM_SMEM);
    cudaFuncSetAttribute(flash_mma, cudaFuncAttributeMaxDynamicSharedMemorySize, FL_SMEM);

    // 1) fused prep (one launch)
    prep<<<PREP_BLOCKS, 256>>>(x, y, Wq, Wkv, Wpr);
    // 2) q = rope(x @ Wq) -> q_h
    gemm_mma<0><<<dim3(CC / 128, (Bz * TX) / 128), 256, GEMM_SMEM>>>(
        p_gx, p_wq, nullptr, Bz * TX, CC, CC, x_t, invf);
    // 3) kv = y @ Wkv -> k_h (RoPE), vt_h (transposed)
    gemm_mma<1><<<dim3(2 * CC / 128, (Bz * TY) / 128), 256, GEMM_SMEM>>>(
        p_gy, p_wkv, nullptr, Bz * TY, 2 * CC, CC, y_t, invf);
    // 4) windowed flash attention (64-query tiles, cp.async pipelined)
    flash_mma<<<dim3(TX / 64, HH, Bz), 128, FL_SMEM>>>(x_t, y_t, dist, mind);
    // 5) out = o @ Wproj
    gemm_mma<2><<<dim3(CC / 128, (Bz * TX) / 128), 256, GEMM_SMEM>>>(
        p_go, p_wp, out, Bz * TX, CC, CC, nullptr, nullptr);
}

// round 15
// speedup vs baseline: 1.6739x; 1.0543x over previous
#include <cuda_runtime.h>
#include <cuda_fp16.h>
#include <math.h>
#include <stdint.h>

#define Bz 2
#define TX 1024
#define TY 4096
#define CC 768
#define HH 12
#define DD 64

// fp16 activations ([M][K] row-major)
__device__ __half gx_h[(size_t)Bz * TX * CC];
__device__ __half gy_h[(size_t)Bz * TY * CC];
__device__ __half go_h[(size_t)Bz * TX * CC];
// transposed weights [N][K] fp16
__device__ __half gwq_h[(size_t)CC * CC];
__device__ __half gwkv_h[(size_t)2 * CC * CC];
__device__ __half gwp_h[(size_t)CC * CC];
// attention operands fp16
__device__ __half q_h[(size_t)Bz * HH * TX * DD];
__device__ __half k_h[(size_t)Bz * HH * TY * DD];
__device__ __half vt_h[(size_t)Bz * HH * DD * TY];  // [b,h,d,t]

__device__ __forceinline__ uint32_t pack_h2(float a, float b) {
    __half2 h = __floats2half2_rn(a, b);
    return *reinterpret_cast<uint32_t*>(&h);
}

__device__ __forceinline__ void cp16(uint32_t saddr, const void* g) {
    asm volatile("cp.async.cg.shared.global [%0], [%1], 16;" :: "r"(saddr), "l"(g));
}

__device__ __forceinline__ void mma_h(float* c, const uint32_t* a, const uint32_t* b) {
    asm volatile(
        "mma.sync.aligned.m16n8k16.row.col.f32.f16.f16.f32 "
        "{%0,%1,%2,%3},{%4,%5,%6,%7},{%8,%9},{%0,%1,%2,%3};"
        : "+f"(c[0]), "+f"(c[1]), "+f"(c[2]), "+f"(c[3])
        : "r"(a[0]), "r"(a[1]), "r"(a[2]), "r"(a[3]), "r"(b[0]), "r"(b[1]));
}

__device__ __forceinline__ void ldsm4(uint32_t& d0, uint32_t& d1, uint32_t& d2,
                                      uint32_t& d3, uint32_t addr) {
    asm volatile("ldmatrix.sync.aligned.m8n8.x4.shared.b16 {%0,%1,%2,%3}, [%4];"
                 : "=r"(d0), "=r"(d1), "=r"(d2), "=r"(d3) : "r"(addr));
}

// ---------------------------------------------------------------------------
// Fused prep (single launch): fcvt(x), fcvt(y), wtrans(Wq/Wkv/Wp).
// ---------------------------------------------------------------------------
#define PREP_BLOCKS 9984

__global__ void __launch_bounds__(256)
prep(const float* __restrict__ x, const float* __restrict__ y,
     const float* __restrict__ Wq, const float* __restrict__ Wkv,
     const float* __restrict__ Wp)
{
    __shared__ float sm[32][33];
    int id = blockIdx.x;
    if (id < 7680) {
        const float* A;
        __half* O;
        int i;
        if (id < 1536) { A = x; O = gx_h; i = id * 256 + threadIdx.x; }
        else           { A = y; O = gy_h; i = (id - 1536) * 256 + threadIdx.x; }
        float4 v = ((const float4*)A)[i];
        ((uint2*)O)[i] = make_uint2(pack_h2(v.x, v.y), pack_h2(v.z, v.w));
        return;
    }
    id -= 7680;
    const float* W;
    __half* T;
    int N;
    if (id < 576)       { W = Wq;  T = gwq_h;  N = 768; }
    else if (id < 1728) { id -= 576;  W = Wkv; T = gwkv_h; N = 1536; }
    else                { id -= 1728; W = Wp;  T = gwp_h;  N = 768; }
    const int K = CC;
    int ntile = N / 32;
    int n0 = (id % ntile) * 32, k0 = (id / ntile) * 32;
    int tx = threadIdx.x & 31, ty = threadIdx.x >> 5;
#pragma unroll
    for (int i = 0; i < 4; i++)
        sm[ty + 8 * i][tx] = W[(size_t)(k0 + ty + 8 * i) * N + n0 + tx];
    __syncthreads();
#pragma unroll
    for (int i = 0; i < 4; i++)
        T[(size_t)(n0 + ty + 8 * i) * K + k0 + tx] = __float2half(sm[tx][ty + 8 * i]);
}

// ---------------------------------------------------------------------------
// fp16 HMMA GEMM, ldmatrix fragment loads. CTA 128x128, 2-stage cp.async.
// MODE 0: RoPE -> q_h   MODE 1: K(RoPE)->k_h, V->vt_h   MODE 2: -> Out fp32
// ---------------------------------------------------------------------------
#define STG_SZ 32768u
#define GEMM_SMEM 65536u

template <int MODE>
__global__ void __launch_bounds__(256, 2)
gemm_mma(const __half* __restrict__ Ah, const __half* __restrict__ Bh,
         float* __restrict__ Out, int M, int N, int K,
         const float* __restrict__ tvec, const float* __restrict__ invf)
{
    extern __shared__ __align__(16) uint8_t smem[];
    const uint32_t sbase = (uint32_t)__cvta_generic_to_shared(smem);
    const int tid = threadIdx.x;
    const int wid = tid >> 5, lane = tid & 31;
    const int wm = wid & 1, wn = wid >> 1;
    const int m0 = blockIdx.y * 128, n0 = blockIdx.x * 128;
    const int lr = lane >> 2, lc = lane & 3;

    // ldmatrix per-thread constants
    const uint32_t lrow = lane & 7;
    const uint32_t rowA = (((uint32_t)lane >> 3) & 1) * 8 + lrow;   // A octets: rows, rows+8, rows/seg+1, rows+8/seg+1
    const uint32_t segA = ((uint32_t)lane >> 4) & 1;
    const uint32_t rowB = (((uint32_t)lane >> 4) & 1) * 8 + lrow;   // B octets: n/seg, n/seg+1, n+8/seg, n+8/seg+1
    const uint32_t segB = ((uint32_t)lane >> 3) & 1;
    uint32_t xorA[4], xorB[4];
#pragma unroll
    for (int s = 0; s < 4; s++) {
        xorA[s] = (((2u * s + segA) ^ lrow) << 4) + rowA * 128u;
        xorB[s] = (((2u * s + segB) ^ lrow) << 4) + rowB * 128u;
    }

    float acc[4][4][4];
#pragma unroll
    for (int a = 0; a < 4; a++)
#pragma unroll
        for (int b = 0; b < 4; b++)
#pragma unroll
            for (int c = 0; c < 4; c++) acc[a][b][c] = 0.f;

    const int NCH = K / 64;  // 12

    auto issue = [&](int ch, int st) {
        const int k0 = ch * 64;
        const uint32_t sa = sbase + (uint32_t)st * STG_SZ;
        const uint32_t sb = sa + 16384u;
#pragma unroll
        for (int it = 0; it < 4; it++) {
            int i = tid + it * 256;
            int r = i >> 3, t = i & 7;
            uint32_t soff = (uint32_t)(r * 128 + ((t ^ (r & 7)) << 4));
            cp16(sa + soff, Ah + (size_t)(m0 + r) * K + k0 + t * 8);
            cp16(sb + soff, Bh + (size_t)(n0 + r) * K + k0 + t * 8);
        }
        asm volatile("cp.async.commit_group;");
    };

    issue(0, 0);
    for (int ch = 0; ch < NCH; ch++) {
        if (ch + 1 < NCH) {
            issue(ch + 1, (ch + 1) & 1);
            asm volatile("cp.async.wait_group 1;");
        } else {
            asm volatile("cp.async.wait_group 0;");
        }
        __syncthreads();

        const uint32_t sA = sbase + (uint32_t)(ch & 1) * STG_SZ;
        const uint32_t sB = sA + 16384u;
#pragma unroll
        for (int s = 0; s < 4; s++) {
            uint32_t bfr[4][2];
#pragma unroll
            for (int ntp = 0; ntp < 2; ntp++) {
                uint32_t d0, d1, d2, d3;
                ldsm4(d0, d1, d2, d3, sB + (uint32_t)(wn * 32 + ntp * 16) * 128u + xorB[s]);
                bfr[2 * ntp][0] = d0;  bfr[2 * ntp][1] = d1;
                bfr[2 * ntp + 1][0] = d2;  bfr[2 * ntp + 1][1] = d3;
            }
#pragma unroll
            for (int mt = 0; mt < 4; mt++) {
                uint32_t af[4];
                ldsm4(af[0], af[1], af[2], af[3],
                      sA + (uint32_t)(wm * 64 + mt * 16) * 128u + xorA[s]);
#pragma unroll
                for (int nt = 0; nt < 4; nt++) mma_h(acc[mt][nt], af, bfr[nt]);
            }
        }
        __syncthreads();
    }

    // ---- epilogue: fragment cols (2lc, 2lc+1) are RoPE pairs ----
#pragma unroll
    for (int mt = 0; mt < 4; mt++) {
        int mA = m0 + wm * 64 + mt * 16 + lr;
#pragma unroll
        for (int half = 0; half < 2; half++) {
            int m = mA + half * 8;
            float pos = 0.f;
            int bb = 0, tt = 0;
            if (MODE == 0) { bb = m / TX; tt = m % TX; pos = tvec[m]; }
            if (MODE == 1) { bb = m / TY; tt = m % TY; pos = tvec[m]; }
#pragma unroll
            for (int nt = 0; nt < 4; nt++) {
                float c0 = acc[mt][nt][half * 2 + 0];
                float c1 = acc[mt][nt][half * 2 + 1];
                int col = n0 + wn * 32 + nt * 8 + 2 * lc;
                if (MODE == 2) {
                    *(float2*)&Out[(size_t)m * N + col] = make_float2(c0, c1);
                } else if (MODE == 0) {
                    int h = col / DD, dd = col % DD;
                    float f = pos * invf[dd >> 1];
                    float sn, cs;
                    sincosf(f, &sn, &cs);
                    size_t idx = ((size_t)(bb * HH + h) * TX + tt) * DD + dd;
                    *(uint32_t*)&q_h[idx] = pack_h2(c0 * cs - c1 * sn, c1 * cs + c0 * sn);
                } else {
                    if (col < CC) {
                        int h = col / DD, dd = col % DD;
                        float f = pos * invf[dd >> 1];
                        float sn, cs;
                        sincosf(f, &sn, &cs);
                        size_t idx = ((size_t)(bb * HH + h) * TY + tt) * DD + dd;
                        *(uint32_t*)&k_h[idx] = pack_h2(c0 * cs - c1 * sn, c1 * cs + c0 * sn);
                    } else {
                        int nv = col - CC;
                        int h = nv / DD, dd = nv % DD;
                        size_t i0 = ((size_t)(bb * HH + h) * DD + dd) * TY + tt;
                        vt_h[i0]      = __float2half(c0);
                        vt_h[i0 + TY] = __float2half(c1);
                    }
                }
            }
        }
    }
}

// ---------------------------------------------------------------------------
// fp16 HMMA flash attention, ldmatrix fragment loads. 64-query tile,
// 128 threads, 2-stage cp.async. Grid (TX/64, H, B) = 384 CTAs.
// ---------------------------------------------------------------------------
#define FST 16640u                 // stage: K 8192 + V 8192 + kt 256
#define FL_RNG (2u * FST)
#define FL_SMEM (FL_RNG + 32u)

__global__ void __launch_bounds__(128)
flash_mma(const float* __restrict__ xt, const float* __restrict__ yt,
          const int* __restrict__ p_dist, const int* __restrict__ p_mind)
{
    extern __shared__ __align__(16) uint8_t sm[];
    const uint32_t sbase = (uint32_t)__cvta_generic_to_shared(sm);
    int* rng = (int*)(sm + FL_RNG);

    const int tid = threadIdx.x;
    const int wid = tid >> 5, lane = tid & 31;
    const int lr = lane >> 2, lc = lane & 3;
    const int q0 = blockIdx.x * 64;
    const int h = blockIdx.y, b = blockIdx.z;
    const float distf = (float)p_dist[0];
    const float mindf = (float)p_mind[0];
    const size_t bh = (size_t)(b * HH + h);

    const __half* Qp = q_h + bh * TX * DD;
    const __half* Kp = k_h + bh * TY * DD;
    const __half* Vp = vt_h + bh * DD * TY;
    const float* Y = yt + (size_t)b * TY;

    const int r0 = q0 + wid * 16 + lr;
    const int r1 = r0 + 8;

    // ldmatrix B-pattern per-thread constants
    const uint32_t lrow = lane & 7;
    const uint32_t rowB = (((uint32_t)lane >> 4) & 1) * 8 + lrow;
    const uint32_t segB = ((uint32_t)lane >> 3) & 1;
    uint32_t xorB[4];
#pragma unroll
    for (int s = 0; s < 4; s++)
        xorB[s] = (((2u * s + segB) ^ lrow) << 4) + rowB * 128u;

    uint32_t qf[4][4];
#pragma unroll
    for (int ks2 = 0; ks2 < 4; ks2++) {
        qf[ks2][0] = *(const uint32_t*)&Qp[(size_t)r0 * DD + 16 * ks2 + 2 * lc];
        qf[ks2][1] = *(const uint32_t*)&Qp[(size_t)r1 * DD + 16 * ks2 + 2 * lc];
        qf[ks2][2] = *(const uint32_t*)&Qp[(size_t)r0 * DD + 16 * ks2 + 8 + 2 * lc];
        qf[ks2][3] = *(const uint32_t*)&Qp[(size_t)r1 * DD + 16 * ks2 + 8 + 2 * lc];
    }
    const float xr0 = xt[(size_t)b * TX + r0] - mindf;
    const float xr1 = xt[(size_t)b * TX + r1] - mindf;

    if (tid == 0) {
        float xmin = xt[(size_t)b * TX + q0] - mindf;
        float xmax = xt[(size_t)b * TX + q0 + 63] - mindf;
        int lo = 0, hi = TY;
        while (lo < hi) { int mid = (lo + hi) >> 1; if (Y[mid] >= xmin - distf) hi = mid; else lo = mid + 1; }
        rng[0] = lo & ~63;
        lo = 0; hi = TY;
        while (lo < hi) { int mid = (lo + hi) >> 1; if (Y[mid] > xmax) hi = mid; else lo = mid + 1; }
        rng[1] = lo;
    }
    __syncthreads();
    const int ksr = rng[0], ker = rng[1];

    auto issue = [&](int kb, int st) {
        const uint32_t sk = sbase + (uint32_t)st * FST;
        const uint32_t sv = sk + 8192u;
#pragma unroll
        for (int it = 0; it < 4; it++) {
            int i = tid + it * 128;
            int r = i >> 3, t = i & 7;
            uint32_t so = (uint32_t)(r * 128 + ((t ^ (r & 7)) << 4));
            cp16(sk + so, Kp + (size_t)(kb + r) * DD + t * 8);
            cp16(sv + so, Vp + (size_t)r * TY + kb + t * 8);
        }
        if (tid < 16) cp16(sk + 16384u + tid * 16u, Y + kb + tid * 4);
        asm volatile("cp.async.commit_group;");
    };

    float m0r = -1e30f, m1r = -1e30f, l0r = 0.f, l1r = 0.f;
    float o[8][4];
#pragma unroll
    for (int i = 0; i < 8; i++)
#pragma unroll
        for (int j = 0; j < 4; j++) o[i][j] = 0.f;

    if (ksr < ker) issue(ksr, 0);
    int st = 0;
    for (int kb = ksr; kb < ker; kb += 64, st ^= 1) {
        if (kb + 64 < ker) {
            issue(kb + 64, st ^ 1);
            asm volatile("cp.async.wait_group 1;");
        } else {
            asm volatile("cp.async.wait_group 0;");
        }
        __syncthreads();

        const uint32_t sk = sbase + (uint32_t)st * FST;
        const uint32_t sv = sk + 8192u;
        float* kt_s = (float*)(sm + (size_t)st * FST + 16384);

        // ---- S = Q K^T ----
        float s[8][4];
#pragma unroll
        for (int i = 0; i < 8; i++)
#pragma unroll
            for (int j = 0; j < 4; j++) s[i][j] = 0.f;
#pragma unroll
        for (int ks2 = 0; ks2 < 4; ks2++) {
#pragma unroll
            for (int ntp = 0; ntp < 4; ntp++) {
                uint32_t d0, d1, d2, d3;
                ldsm4(d0, d1, d2, d3, sk + (uint32_t)(ntp * 16) * 128u + xorB[ks2]);
                uint32_t b0[2] = {d0, d1}, b1[2] = {d2, d3};
                mma_h(s[2 * ntp], qf[ks2], b0);
                mma_h(s[2 * ntp + 1], qf[ks2], b1);
            }
        }

        // ---- mask + scale ----
#pragma unroll
        for (int nt = 0; nt < 8; nt++) {
#pragma unroll
            for (int j = 0; j < 2; j++) {
                float yv = kt_s[nt * 8 + 2 * lc + j];
                bool ok0 = (xr0 >= yv) && (xr0 <= yv + distf);
                bool ok1 = (xr1 >= yv) && (xr1 <= yv + distf);
                s[nt][j]     = ok0 ? s[nt][j] * 0.125f     : -1e30f;
                s[nt][j + 2] = ok1 ? s[nt][j + 2] * 0.125f : -1e30f;
            }
        }
        // ---- online softmax ----
        float mx0 = -1e30f, mx1 = -1e30f;
#pragma unroll
        for (int nt = 0; nt < 8; nt++) {
            mx0 = fmaxf(mx0, fmaxf(s[nt][0], s[nt][1]));
            mx1 = fmaxf(mx1, fmaxf(s[nt][2], s[nt][3]));
        }
        mx0 = fmaxf(mx0, __shfl_xor_sync(0xffffffffu, mx0, 1));
        mx0 = fmaxf(mx0, __shfl_xor_sync(0xffffffffu, mx0, 2));
        mx1 = fmaxf(mx1, __shfl_xor_sync(0xffffffffu, mx1, 1));
        mx1 = fmaxf(mx1, __shfl_xor_sync(0xffffffffu, mx1, 2));
        float mn0 = fmaxf(m0r, mx0), mn1 = fmaxf(m1r, mx1);
        float f0 = __expf(m0r - mn0), f1 = __expf(m1r - mn1);

        uint32_t pp[8][2];
        float sum0 = 0.f, sum1 = 0.f;
#pragma unroll
        for (int nt = 0; nt < 8; nt++) {
            float p00 = (s[nt][0] <= -1e29f) ? 0.f : __expf(s[nt][0] - mn0);
            float p01 = (s[nt][1] <= -1e29f) ? 0.f : __expf(s[nt][1] - mn0);
            float p10 = (s[nt][2] <= -1e29f) ? 0.f : __expf(s[nt][2] - mn1);
            float p11 = (s[nt][3] <= -1e29f) ? 0.f : __expf(s[nt][3] - mn1);
            sum0 += p00 + p01;
            sum1 += p10 + p11;
            pp[nt][0] = pack_h2(p00, p01);
            pp[nt][1] = pack_h2(p10, p11);
        }
        sum0 += __shfl_xor_sync(0xffffffffu, sum0, 1);
        sum0 += __shfl_xor_sync(0xffffffffu, sum0, 2);
        sum1 += __shfl_xor_sync(0xffffffffu, sum1, 1);
        sum1 += __shfl_xor_sync(0xffffffffu, sum1, 2);
        l0r = l0r * f0 + sum0;
        l1r = l1r * f1 + sum1;
        m0r = mn0;
        m1r = mn1;
#pragma unroll
        for (int nd = 0; nd < 8; nd++) {
            o[nd][0] *= f0; o[nd][1] *= f0;
            o[nd][2] *= f1; o[nd][3] *= f1;
        }

        // ---- O += P V ----
#pragma unroll
        for (int kp = 0; kp < 4; kp++) {
            uint32_t af[4] = {pp[2 * kp][0], pp[2 * kp][1], pp[2 * kp + 1][0], pp[2 * kp + 1][1]};
#pragma unroll
            for (int ndp = 0; ndp < 4; ndp++) {
                uint32_t d0, d1, d2, d3;
                ldsm4(d0, d1, d2, d3, sv + (uint32_t)(ndp * 16) * 128u + xorB[kp]);
                uint32_t b0[2] = {d0, d1}, b1[2] = {d2, d3};
                mma_h(o[2 * ndp], af, b0);
                mma_h(o[2 * ndp + 1], af, b1);
            }
        }
        __syncthreads();
    }

    // ---- epilogue: O/l -> go_h fp16 ----
    float rc0 = (l0r > 0.f) ? 1.f / l0r : 0.f;
    float rc1 = (l1r > 0.f) ? 1.f / l1r : 0.f;
#pragma unroll
    for (int nd = 0; nd < 8; nd++) {
        int d0 = nd * 8 + 2 * lc;
        size_t i0 = ((size_t)b * TX + r0) * CC + h * DD + d0;
        *(uint32_t*)&go_h[i0] = pack_h2(o[nd][0] * rc0, o[nd][1] * rc0);
        size_t i1 = ((size_t)b * TX + r1) * CC + h * DD + d0;
        *(uint32_t*)&go_h[i1] = pack_h2(o[nd][2] * rc1, o[nd][3] * rc1);
    }
}

extern "C" void kernel_launch(void* const* d_in, const int* in_sizes, int n_in,
                              void* d_out, int out_size) {
    const float* x    = (const float*)d_in[0];
    const float* x_t  = (const float*)d_in[1];
    const float* y    = (const float*)d_in[2];
    const float* y_t  = (const float*)d_in[3];
    const int*   dist = (const int*)d_in[4];
    const int*   mind = (const int*)d_in[5];
    const float* Wq   = (const float*)d_in[6];
    const float* Wkv  = (const float*)d_in[7];
    const float* Wpr  = (const float*)d_in[8];
    const float* invf = (const float*)d_in[9];
    float* out = (float*)d_out;

    __half *p_gx, *p_gy, *p_go, *p_wq, *p_wkv, *p_wp;
    cudaGetSymbolAddress((void**)&p_gx, gx_h);
    cudaGetSymbolAddress((void**)&p_gy, gy_h);
    cudaGetSymbolAddress((void**)&p_go, go_h);
    cudaGetSymbolAddress((void**)&p_wq, gwq_h);
    cudaGetSymbolAddress((void**)&p_wkv, gwkv_h);
    cudaGetSymbolAddress((void**)&p_wp, gwp_h);

    cudaFuncSetAttribute(gemm_mma<0>, cudaFuncAttributeMaxDynamicSharedMemorySize, GEMM_SMEM);
    cudaFuncSetAttribute(gemm_mma<1>, cudaFuncAttributeMaxDynamicSharedMemorySize, GEMM_SMEM);
    cudaFuncSetAttribute(gemm_mma<2>, cudaFuncAttributeMaxDynamicSharedMemorySize, GEMM_SMEM);
    cudaFuncSetAttribute(flash_mma, cudaFuncAttributeMaxDynamicSharedMemorySize, FL_SMEM);

    // 1) fused prep (one launch)
    prep<<<PREP_BLOCKS, 256>>>(x, y, Wq, Wkv, Wpr);
    // 2) q = rope(x @ Wq) -> q_h
    gemm_mma<0><<<dim3(CC / 128, (Bz * TX) / 128), 256, GEMM_SMEM>>>(
        p_gx, p_wq, nullptr, Bz * TX, CC, CC, x_t, invf);
    // 3) kv = y @ Wkv -> k_h (RoPE), vt_h (transposed)
    gemm_mma<1><<<dim3(2 * CC / 128, (Bz * TY) / 128), 256, GEMM_SMEM>>>(
        p_gy, p_wkv, nullptr, Bz * TY, 2 * CC, CC, y_t, invf);
    // 4) windowed flash attention (ldmatrix + cp.async)
    flash_mma<<<dim3(TX / 64, HH, Bz), 128, FL_SMEM>>>(x_t, y_t, dist, mind);
    // 5) out = o @ Wproj
    gemm_mma<2><<<dim3(CC / 128, (Bz * TX) / 128), 256, GEMM_SMEM>>>(
        p_go, p_wp, out, Bz * TX, CC, CC, nullptr, nullptr);
}